// round 3
// baseline (speedup 1.0000x reference)
#include <cuda_runtime.h>
#include <cuda_bf16.h>
#include <mma.h>

using namespace nvcuda;

#define B_SZ 65536
#define D_SZ 256
#define F_SZ 512
#define P_SZ 256

// ---------------- scratch (static device globals; no allocations) ----------------
__device__ __nv_bfloat16 g_W1[P_SZ * F_SZ];   // theta*pw + alpha*pp
__device__ __nv_bfloat16 g_W2[P_SZ * F_SZ];   // beta*pw
__device__ float         g_biasP[P_SZ];       // -beta * pws[p]

// ===================== kernel 1: p-side precompute (tf32 wmma) =====================
// grid = P/16 = 16 CTAs; per CTA: 16 prototype rows x all F=512 cols.
// 8 warps, warp w -> f-slab w*64, warp tile 16x64.
__global__ __launch_bounds__(256, 1)
void pside_kernel(const float* __restrict__ prototypes,
                  const float* __restrict__ features,
                  const float* __restrict__ alpha,
                  const float* __restrict__ beta,
                  const float* __restrict__ theta) {
    extern __shared__ float smp[];   // ps (16x256, 16KB) + Outs (16x512, 32KB)
    float* ps   = smp;
    float* Outs = smp + 16 * D_SZ;

    int tid  = threadIdx.x;
    int warp = tid >> 5;
    int lane = tid & 31;
    int p0   = blockIdx.x * 16;

    {
        const float4* src = (const float4*)(prototypes + (size_t)p0 * D_SZ);
        float4* dst = (float4*)ps;
        for (int i = tid; i < 16 * D_SZ / 4; i += 256) dst[i] = src[i];
    }
    __syncthreads();

    using FragA = wmma::fragment<wmma::matrix_a, 16, 16, 8, wmma::precision::tf32, wmma::row_major>;
    using FragB = wmma::fragment<wmma::matrix_b, 16, 16, 8, wmma::precision::tf32, wmma::col_major>;
    using FragC = wmma::fragment<wmma::accumulator, 16, 16, 8, float>;

    FragC c[4];
#pragma unroll
    for (int j = 0; j < 4; j++) wmma::fill_fragment(c[j], 0.f);

    int f0 = warp * 64;
#pragma unroll 4
    for (int k0 = 0; k0 < D_SZ; k0 += 8) {
        FragA a;
        wmma::load_matrix_sync(a, ps + k0, D_SZ);
#pragma unroll
        for (int e = 0; e < a.num_elements; e++) a.x[e] = wmma::__float_to_tf32(a.x[e]);
#pragma unroll
        for (int j = 0; j < 4; j++) {
            FragB b;
            wmma::load_matrix_sync(b, features + (size_t)(f0 + j * 16) * D_SZ + k0, D_SZ);
#pragma unroll
            for (int e = 0; e < b.num_elements; e++) b.x[e] = wmma::__float_to_tf32(b.x[e]);
            wmma::mma_sync(c[j], a, b, c[j]);
        }
    }
#pragma unroll
    for (int j = 0; j < 4; j++)
        wmma::store_matrix_sync(Outs + f0 + j * 16, c[j], F_SZ, wmma::mem_row_major);
    __syncthreads();

    float a_ = alpha[0], b_ = beta[0], th = theta[0];
    for (int i = tid; i < 16 * F_SZ; i += 256) {
        int pr = i >> 9, f = i & 511;
        float acc = Outs[i];
        float pp = fmaxf(acc, 0.f);
        float pw = acc * pp;
        g_W1[(size_t)(p0 + pr) * F_SZ + f] = __float2bfloat16(th * pw + a_ * pp);
        g_W2[(size_t)(p0 + pr) * F_SZ + f] = __float2bfloat16(b_ * pw);
    }
    // pws rows: warp w -> rows w*2, w*2+1
    for (int r = warp * 2; r < warp * 2 + 2; r++) {
        float s = 0.f;
        for (int cix = lane; cix < F_SZ; cix += 32) {
            float acc = Outs[r * F_SZ + cix];
            s += acc * fmaxf(acc, 0.f);
        }
#pragma unroll
        for (int o = 16; o > 0; o >>= 1) s += __shfl_xor_sync(0xffffffffu, s, o);
        if (lane == 0) g_biasP[p0 + r] = -b_ * s;
    }
}

// ===================== kernel 2: fused stage1+stage2, 64-row CTAs, 2 CTA/SM =====================
// smem layout (dynamic, ~105.25 KB):
//   [0, 64K)        Rs   bf16[64][512]    (phase B epilogue reuses as Os fp32[64][256])
//   [64K, 96K)      buf: phase A = xs fp32[64][128] (k-chunk); phase B = Ws1/Ws2 bf16[256][32] each
//   [96K, +256)     rb   fp32[64]
//   [.., +1K)       bp   fp32[256]
//   [.., +8K)       stw  fp32[8][256]
#define RS_OFF   0
#define BUF_OFF  (64 * 1024)
#define RB_OFF   (96 * 1024)
#define BP_OFF   (RB_OFF + 256)
#define STW_OFF  (BP_OFF + 1024)
#define SMEM_FUSED (STW_OFF + 8 * 256 * 4)

__global__ __launch_bounds__(256, 2)
void fused_kernel(const float* __restrict__ x,
                  const float* __restrict__ features,
                  const float* __restrict__ alpha,
                  float* __restrict__ out) {
    extern __shared__ char smraw[];
    __nv_bfloat16* Rs = (__nv_bfloat16*)(smraw + RS_OFF);
    float*         rb = (float*)(smraw + RB_OFF);
    float*         bp = (float*)(smraw + BP_OFF);

    int tid  = threadIdx.x;
    int warp = tid >> 5;
    int lane = tid & 31;
    int m0   = blockIdx.x * 64;

    // ---------------- Phase A: R = relu(x @ F^T), tf32, two F-passes ----------------
    using FA1 = wmma::fragment<wmma::matrix_a, 16, 16, 8, wmma::precision::tf32, wmma::row_major>;
    using FB1 = wmma::fragment<wmma::matrix_b, 16, 16, 8, wmma::precision::tf32, wmma::col_major>;
    using FC1 = wmma::fragment<wmma::accumulator, 16, 16, 8, float>;

    for (int fpass = 0; fpass < 2; fpass++) {
        FC1 c[4][2];                      // warp tile 64 rows x 32 cols
#pragma unroll
        for (int i = 0; i < 4; i++)
#pragma unroll
            for (int j = 0; j < 2; j++) wmma::fill_fragment(c[i][j], 0.f);

        int f0 = fpass * 256 + warp * 32;

        for (int kc = 0; kc < 2; kc++) {
            float* xs = (float*)(smraw + BUF_OFF);   // [64][128] fp32, 32 KB
            __syncthreads();
            {
                // x rows m0..m0+63, cols kc*128..+128
                const float* src = x + (size_t)m0 * D_SZ + kc * 128;
                float4* dst = (float4*)xs;
                for (int i = tid; i < 64 * 128 / 4; i += 256) {
                    int row = i >> 5, q = i & 31;     // 32 float4 per row
                    dst[i] = ((const float4*)(src + (size_t)row * D_SZ))[q];
                }
            }
            __syncthreads();

#pragma unroll 4
            for (int k0 = 0; k0 < 128; k0 += 8) {
                FA1 a[4];
#pragma unroll
                for (int i = 0; i < 4; i++) {
                    wmma::load_matrix_sync(a[i], xs + (i * 16) * 128 + k0, 128);
#pragma unroll
                    for (int e = 0; e < a[i].num_elements; e++)
                        a[i].x[e] = wmma::__float_to_tf32(a[i].x[e]);
                }
#pragma unroll
                for (int j = 0; j < 2; j++) {
                    FB1 b;
                    wmma::load_matrix_sync(b, features + (size_t)(f0 + j * 16) * D_SZ + kc * 128 + k0, D_SZ);
#pragma unroll
                    for (int e = 0; e < b.num_elements; e++)
                        b.x[e] = wmma::__float_to_tf32(b.x[e]);
#pragma unroll
                    for (int i = 0; i < 4; i++) wmma::mma_sync(c[i][j], a[i], b, c[i][j]);
                }
            }
        }

        // epilogue: frags -> stw -> relu -> bf16 Rs
        float* stw = (float*)(smraw + STW_OFF) + warp * 256;
#pragma unroll
        for (int i = 0; i < 4; i++) {
#pragma unroll
            for (int j = 0; j < 2; j++) {
                wmma::store_matrix_sync(stw, c[i][j], 16, wmma::mem_row_major);
                __syncwarp();
#pragma unroll
                for (int e = 0; e < 8; e++) {
                    int idx = lane * 8 + e;
                    int rr = idx >> 4, cc = idx & 15;
                    float v = fmaxf(stw[idx], 0.f);
                    Rs[(i * 16 + rr) * F_SZ + f0 + j * 16 + cc] = __float2bfloat16(v);
                }
                __syncwarp();
            }
        }
    }
    __syncthreads();   // Rs fully written

    // row bias: rb[r] = -alpha * sum_f r^2 (warp w -> rows w*8..+8)
    {
        float av = alpha[0];
        for (int r = warp * 8; r < warp * 8 + 8; r++) {
            float s = 0.f;
            for (int cix = lane; cix < F_SZ; cix += 32) {
                float v = __bfloat162float(Rs[r * F_SZ + cix]);
                s += v * v;
            }
#pragma unroll
            for (int o = 16; o > 0; o >>= 1) s += __shfl_xor_sync(0xffffffffu, s, o);
            if (lane == 0) rb[r] = -av * s;
        }
    }

    // ---------------- Phase B: out = [R^2|R] @ [W1|W2]^T, bf16 ----------------
    using FA2 = wmma::fragment<wmma::matrix_a, 16, 16, 16, __nv_bfloat16, wmma::row_major>;
    using FB2 = wmma::fragment<wmma::matrix_b, 16, 16, 16, __nv_bfloat16, wmma::col_major>;
    using FC2 = wmma::fragment<wmma::accumulator, 16, 16, 16, float>;

    __nv_bfloat16* Ws1 = (__nv_bfloat16*)(smraw + BUF_OFF);   // [256][32] bf16, 16 KB
    __nv_bfloat16* Ws2 = Ws1 + P_SZ * 32;                     // [256][32] bf16, 16 KB

    int wm = warp >> 2;      // 0..1 -> 32-row slab
    int wn = warp & 3;       // 0..3 -> 64-col slab
    int mrow = wm * 32, ncol = wn * 64;

    FC2 c2[2][4];
#pragma unroll
    for (int i = 0; i < 2; i++)
#pragma unroll
        for (int j = 0; j < 4; j++) wmma::fill_fragment(c2[i][j], 0.f);

    for (int kc = 0; kc < F_SZ; kc += 32) {
        __syncthreads();
        {
            float4* w1 = (float4*)Ws1;
            float4* w2 = (float4*)Ws2;
            for (int i = tid; i < P_SZ * 4; i += 256) {    // 4 float4 (=32 bf16) per row
                int n = i >> 2, q = i & 3;
                w1[i] = ((const float4*)(g_W1 + (size_t)n * F_SZ + kc))[q];
                w2[i] = ((const float4*)(g_W2 + (size_t)n * F_SZ + kc))[q];
            }
        }
        __syncthreads();

#pragma unroll
        for (int k0 = 0; k0 < 32; k0 += 16) {
            FA2 a[2], a2[2];
#pragma unroll
            for (int i = 0; i < 2; i++) {
                wmma::load_matrix_sync(a[i], Rs + (mrow + i * 16) * F_SZ + kc + k0, F_SZ);
#pragma unroll
                for (int e = 0; e < a[i].num_elements; e++)
                    a2[i].x[e] = a[i].x[e] * a[i].x[e];
            }
#pragma unroll
            for (int j = 0; j < 4; j++) {
                FB2 b1, b2;
                wmma::load_matrix_sync(b1, Ws1 + (ncol + j * 16) * 32 + k0, 32);
                wmma::load_matrix_sync(b2, Ws2 + (ncol + j * 16) * 32 + k0, 32);
#pragma unroll
                for (int i = 0; i < 2; i++) {
                    wmma::mma_sync(c2[i][j], a2[i], b1, c2[i][j]);
                    wmma::mma_sync(c2[i][j], a[i], b2, c2[i][j]);
                }
            }
        }
    }

    // bias copy + epilogue
    if (tid < P_SZ) bp[tid] = g_biasP[tid];
    __syncthreads();   // Rs dead -> Os takes over; bp ready

    float* Os = (float*)(smraw + RS_OFF);   // [64][256] fp32 = 64 KB
#pragma unroll
    for (int i = 0; i < 2; i++)
#pragma unroll
        for (int j = 0; j < 4; j++)
            wmma::store_matrix_sync(Os + (mrow + i * 16) * P_SZ + ncol + j * 16, c2[i][j],
                                    P_SZ, wmma::mem_row_major);
    __syncthreads();

    for (int i = tid; i < 64 * P_SZ; i += 256) {
        int r = i >> 8;
        int p = i & 255;
        out[(size_t)(m0 + r) * P_SZ + p] = Os[i] + rb[r] + bp[p];
    }
}

// =========================== launch ===========================
extern "C" void kernel_launch(void* const* d_in, const int* in_sizes, int n_in,
                              void* d_out, int out_size) {
    const float* x          = (const float*)d_in[0];
    const float* features   = (const float*)d_in[1];
    const float* prototypes = (const float*)d_in[2];
    const float* alpha      = (const float*)d_in[3];
    const float* beta       = (const float*)d_in[4];
    const float* theta      = (const float*)d_in[5];
    float* out = (float*)d_out;

    cudaFuncSetAttribute(pside_kernel, cudaFuncAttributeMaxDynamicSharedMemorySize, 48 * 1024);
    cudaFuncSetAttribute(fused_kernel, cudaFuncAttributeMaxDynamicSharedMemorySize, SMEM_FUSED);

    pside_kernel<<<P_SZ / 16, 256, 48 * 1024>>>(prototypes, features, alpha, beta, theta);
    fused_kernel<<<B_SZ / 64, 256, SMEM_FUSED>>>(x, features, alpha, out);
}

// round 4
// speedup vs baseline: 2.3897x; 2.3897x over previous
#include <cuda_runtime.h>
#include <cuda_bf16.h>
#include <mma.h>

using namespace nvcuda;

#define B_SZ 65536
#define D_SZ 256
#define F_SZ 512
#define P_SZ 256

// padded smem strides (all ≡ 1 mod 8 in 16B units → conflict-free LDSM)
#define RS_LD  520   // bf16, 1040B
#define XS_LD  260   // fp32, 1040B
#define WS_LD  72    // bf16, 144B
#define OS_LD  260   // fp32, 1040B

// ---------------- scratch (static device globals; no allocations) ----------------
__device__ __nv_bfloat16 g_W1[P_SZ * F_SZ];   // theta*pw + alpha*pp
__device__ __nv_bfloat16 g_W2[P_SZ * F_SZ];   // beta*pw
__device__ float         g_biasP[P_SZ];       // -beta * pws[p]

// ===================== kernel 1: p-side precompute (tf32 wmma) =====================
__global__ __launch_bounds__(256, 1)
void pside_kernel(const float* __restrict__ prototypes,
                  const float* __restrict__ features,
                  const float* __restrict__ alpha,
                  const float* __restrict__ beta,
                  const float* __restrict__ theta) {
    extern __shared__ float smp[];   // ps (16x260 fp32) + Outs (16x512 fp32)
    float* ps   = smp;               // padded stride
    float* Outs = smp + 16 * XS_LD;

    int tid  = threadIdx.x;
    int warp = tid >> 5;
    int lane = tid & 31;
    int p0   = blockIdx.x * 16;

    {
        const float4* src = (const float4*)(prototypes + (size_t)p0 * D_SZ);
        for (int i = tid; i < 16 * D_SZ / 4; i += 256) {
            int row = i >> 6, q = i & 63;
            ((float4*)(ps + row * XS_LD))[q] = src[(size_t)row * 64 + q];
        }
    }
    __syncthreads();

    using FragA = wmma::fragment<wmma::matrix_a, 16, 16, 8, wmma::precision::tf32, wmma::row_major>;
    using FragB = wmma::fragment<wmma::matrix_b, 16, 16, 8, wmma::precision::tf32, wmma::col_major>;
    using FragC = wmma::fragment<wmma::accumulator, 16, 16, 8, float>;

    FragC c[4];
#pragma unroll
    for (int j = 0; j < 4; j++) wmma::fill_fragment(c[j], 0.f);

    int f0 = warp * 64;
#pragma unroll 4
    for (int k0 = 0; k0 < D_SZ; k0 += 8) {
        FragA a;
        wmma::load_matrix_sync(a, ps + k0, XS_LD);
#pragma unroll
        for (int e = 0; e < a.num_elements; e++) a.x[e] = wmma::__float_to_tf32(a.x[e]);
#pragma unroll
        for (int j = 0; j < 4; j++) {
            FragB b;
            wmma::load_matrix_sync(b, features + (size_t)(f0 + j * 16) * D_SZ + k0, D_SZ);
#pragma unroll
            for (int e = 0; e < b.num_elements; e++) b.x[e] = wmma::__float_to_tf32(b.x[e]);
            wmma::mma_sync(c[j], a, b, c[j]);
        }
    }
#pragma unroll
    for (int j = 0; j < 4; j++)
        wmma::store_matrix_sync(Outs + f0 + j * 16, c[j], F_SZ, wmma::mem_row_major);
    __syncthreads();

    float a_ = alpha[0], b_ = beta[0], th = theta[0];
    for (int i = tid; i < 16 * F_SZ; i += 256) {
        int pr = i >> 9, f = i & 511;
        float acc = Outs[i];
        float pp = fmaxf(acc, 0.f);
        float pw = acc * pp;
        g_W1[(size_t)(p0 + pr) * F_SZ + f] = __float2bfloat16(th * pw + a_ * pp);
        g_W2[(size_t)(p0 + pr) * F_SZ + f] = __float2bfloat16(b_ * pw);
    }
    for (int r = warp * 2; r < warp * 2 + 2; r++) {
        float s = 0.f;
        for (int cix = lane; cix < F_SZ; cix += 32) {
            float acc = Outs[r * F_SZ + cix];
            s += acc * fmaxf(acc, 0.f);
        }
#pragma unroll
        for (int o = 16; o > 0; o >>= 1) s += __shfl_xor_sync(0xffffffffu, s, o);
        if (lane == 0) g_biasP[p0 + r] = -b_ * s;
    }
}

// ===================== kernel 2: fused stage1+stage2 (128-row CTAs, padded smem) =====================
// smem layout (dynamic):
//   [0, RS_BYTES)       Rs   bf16[128][RS_LD]    (phase B epilogue reuses as Os fp32[128][OS_LD])
//   [BUF_OFF, ..)       buf: phase A = xs fp32[64][XS_LD]; phase B = Ws1/Ws2 bf16[256][WS_LD]
//   rb fp32[128], bp fp32[256], stw fp32[8][256]
#define RS_BYTES  (128 * RS_LD * 2)                 // 133,120
#define BUF_OFF   RS_BYTES
#define BUF_BYTES (2 * P_SZ * WS_LD * 2)            // 73,728 (>= xs 66,560)
#define RB_OFF    (BUF_OFF + BUF_BYTES)
#define BP_OFF    (RB_OFF + 512)
#define STW_OFF   (BP_OFF + 1024)
#define SMEM_FUSED (STW_OFF + 8 * 256 * 4)          // ≈ 216.6 KB

__global__ __launch_bounds__(256, 1)
void fused_kernel(const float* __restrict__ x,
                  const float* __restrict__ features,
                  const float* __restrict__ alpha,
                  float* __restrict__ out) {
    extern __shared__ char smraw[];
    __nv_bfloat16* Rs = (__nv_bfloat16*)smraw;
    float*         rb = (float*)(smraw + RB_OFF);
    float*         bp = (float*)(smraw + BP_OFF);

    int tid  = threadIdx.x;
    int warp = tid >> 5;
    int lane = tid & 31;
    int m0   = blockIdx.x * 128;

    // ---------------- Phase A: R = relu(x @ F^T), tf32, two 64-row halves ----------------
    using FA1 = wmma::fragment<wmma::matrix_a, 16, 16, 8, wmma::precision::tf32, wmma::row_major>;
    using FB1 = wmma::fragment<wmma::matrix_b, 16, 16, 8, wmma::precision::tf32, wmma::col_major>;
    using FC1 = wmma::fragment<wmma::accumulator, 16, 16, 8, float>;

    for (int h = 0; h < 2; h++) {
        float* xs = (float*)(smraw + BUF_OFF);   // [64][XS_LD] fp32
        {
            const float4* src = (const float4*)(x + (size_t)(m0 + h * 64) * D_SZ);
            for (int i = tid; i < 64 * D_SZ / 4; i += 256) {
                int row = i >> 6, q = i & 63;    // 64 float4 per row
                ((float4*)(xs + row * XS_LD))[q] = src[(size_t)row * 64 + q];
            }
        }
        __syncthreads();

        FC1 c[4][4];
#pragma unroll
        for (int i = 0; i < 4; i++)
#pragma unroll
            for (int j = 0; j < 4; j++) wmma::fill_fragment(c[i][j], 0.f);

        int f0 = warp * 64;
#pragma unroll 4
        for (int k0 = 0; k0 < D_SZ; k0 += 8) {
            FA1 a[4];
#pragma unroll
            for (int i = 0; i < 4; i++) {
                wmma::load_matrix_sync(a[i], xs + (i * 16) * XS_LD + k0, XS_LD);
#pragma unroll
                for (int e = 0; e < a[i].num_elements; e++)
                    a[i].x[e] = wmma::__float_to_tf32(a[i].x[e]);
            }
#pragma unroll
            for (int j = 0; j < 4; j++) {
                FB1 b;
                wmma::load_matrix_sync(b, features + (size_t)(f0 + j * 16) * D_SZ + k0, D_SZ);
#pragma unroll
                for (int e = 0; e < b.num_elements; e++)
                    b.x[e] = wmma::__float_to_tf32(b.x[e]);
#pragma unroll
                for (int i = 0; i < 4; i++) wmma::mma_sync(c[i][j], a[i], b, c[i][j]);
            }
        }

        // per-warp epilogue: frags -> stw -> relu -> bf16 Rs
        float* stw = (float*)(smraw + STW_OFF) + warp * 256;
#pragma unroll
        for (int i = 0; i < 4; i++) {
#pragma unroll
            for (int j = 0; j < 4; j++) {
                wmma::store_matrix_sync(stw, c[i][j], 16, wmma::mem_row_major);
                __syncwarp();
#pragma unroll
                for (int e = 0; e < 8; e++) {
                    int idx = lane * 8 + e;
                    int rr = idx >> 4, cc = idx & 15;
                    float v = fmaxf(stw[idx], 0.f);
                    Rs[(h * 64 + i * 16 + rr) * RS_LD + f0 + j * 16 + cc] = __float2bfloat16(v);
                }
                __syncwarp();
            }
        }
        __syncthreads();   // xs reload on next half / Rs half complete
    }

    // row bias: rb[r] = -alpha * sum_f r^2
    {
        float av = alpha[0];
        for (int r = warp * 16; r < warp * 16 + 16; r++) {
            float s = 0.f;
            for (int cix = lane; cix < F_SZ; cix += 32) {
                float v = __bfloat162float(Rs[r * RS_LD + cix]);
                s += v * v;
            }
#pragma unroll
            for (int o = 16; o > 0; o >>= 1) s += __shfl_xor_sync(0xffffffffu, s, o);
            if (lane == 0) rb[r] = -av * s;
        }
    }

    // ---------------- Phase B: out = [R^2|R] @ [W1|W2]^T, bf16, 64x64 warp tiles ----------------
    using FA2 = wmma::fragment<wmma::matrix_a, 16, 16, 16, __nv_bfloat16, wmma::row_major>;
    using FB2 = wmma::fragment<wmma::matrix_b, 16, 16, 16, __nv_bfloat16, wmma::col_major>;
    using FC2 = wmma::fragment<wmma::accumulator, 16, 16, 16, float>;

    __nv_bfloat16* Ws1 = (__nv_bfloat16*)(smraw + BUF_OFF);   // [256][WS_LD]
    __nv_bfloat16* Ws2 = Ws1 + P_SZ * WS_LD;

    int wm = warp >> 2;      // 0..1 -> 64-row slab
    int wn = warp & 3;       // 0..3 -> 64-col slab
    int mrow = wm * 64, ncol = wn * 64;

    FC2 c2[4][4];
#pragma unroll
    for (int i = 0; i < 4; i++)
#pragma unroll
        for (int j = 0; j < 4; j++) wmma::fill_fragment(c2[i][j], 0.f);

    for (int kc = 0; kc < F_SZ; kc += 64) {
        __syncthreads();
        {
            for (int i = tid; i < P_SZ * 8; i += 256) {   // 8 float4 (=64 bf16) per row
                int n = i >> 3, q = i & 7;
                ((float4*)(Ws1 + n * WS_LD))[q] = ((const float4*)(g_W1 + (size_t)n * F_SZ + kc))[q];
                ((float4*)(Ws2 + n * WS_LD))[q] = ((const float4*)(g_W2 + (size_t)n * F_SZ + kc))[q];
            }
        }
        __syncthreads();

#pragma unroll
        for (int k0 = 0; k0 < 64; k0 += 16) {
            FA2 a[4], a2[4];
#pragma unroll
            for (int i = 0; i < 4; i++) {
                wmma::load_matrix_sync(a[i], Rs + (mrow + i * 16) * RS_LD + kc + k0, RS_LD);
#pragma unroll
                for (int e = 0; e < a[i].num_elements; e++)
                    a2[i].x[e] = a[i].x[e] * a[i].x[e];
            }
#pragma unroll
            for (int j = 0; j < 4; j++) {
                FB2 b1, b2;
                wmma::load_matrix_sync(b1, Ws1 + (ncol + j * 16) * WS_LD + k0, WS_LD);
                wmma::load_matrix_sync(b2, Ws2 + (ncol + j * 16) * WS_LD + k0, WS_LD);
#pragma unroll
                for (int i = 0; i < 4; i++) {
                    wmma::mma_sync(c2[i][j], a2[i], b1, c2[i][j]);
                    wmma::mma_sync(c2[i][j], a[i], b2, c2[i][j]);
                }
            }
        }
    }

    if (tid < P_SZ) bp[tid] = g_biasP[tid];
    __syncthreads();   // Rs dead -> Os takes over; bp ready

    float* Os = (float*)smraw;   // [128][OS_LD] fp32 (133,120 B = RS_BYTES)
#pragma unroll
    for (int i = 0; i < 4; i++)
#pragma unroll
        for (int j = 0; j < 4; j++)
            wmma::store_matrix_sync(Os + (mrow + i * 16) * OS_LD + ncol + j * 16, c2[i][j],
                                    OS_LD, wmma::mem_row_major);
    __syncthreads();

    for (int i = tid; i < 128 * P_SZ; i += 256) {
        int r = i >> 8;
        int p = i & 255;
        out[(size_t)(m0 + r) * P_SZ + p] = Os[r * OS_LD + p] + rb[r] + bp[p];
    }
}

// =========================== launch ===========================
extern "C" void kernel_launch(void* const* d_in, const int* in_sizes, int n_in,
                              void* d_out, int out_size) {
    const float* x          = (const float*)d_in[0];
    const float* features   = (const float*)d_in[1];
    const float* prototypes = (const float*)d_in[2];
    const float* alpha      = (const float*)d_in[3];
    const float* beta       = (const float*)d_in[4];
    const float* theta      = (const float*)d_in[5];
    float* out = (float*)d_out;

    cudaFuncSetAttribute(pside_kernel, cudaFuncAttributeMaxDynamicSharedMemorySize, 64 * 1024);
    cudaFuncSetAttribute(fused_kernel, cudaFuncAttributeMaxDynamicSharedMemorySize, SMEM_FUSED);

    pside_kernel<<<P_SZ / 16, 256, 64 * 1024>>>(prototypes, features, alpha, beta, theta);
    fused_kernel<<<B_SZ / 128, 256, SMEM_FUSED>>>(x, features, alpha, out);
}

// round 6
// speedup vs baseline: 2.4493x; 1.0250x over previous
#include <cuda_runtime.h>
#include <cuda_bf16.h>
#include <mma.h>

using namespace nvcuda;

#define B_SZ 65536
#define D_SZ 256
#define F_SZ 512
#define P_SZ 256

// padded smem strides — all row strides odd in 16B units => conflict-free LDSM
#define RS_LD  520   // bf16: 1040B = 65 units
#define XS_LD  132   // fp32: 528B  = 33 units
#define WS_LD  40    // bf16: 80B   = 5 units
#define OS_LD  260   // fp32: 1040B = 65 units
#define PS_LD  260   // pside fp32

// ---------------- scratch (static device globals; no allocations) ----------------
__device__ __nv_bfloat16 g_W1[P_SZ * F_SZ];   // theta*pw + alpha*pp
__device__ __nv_bfloat16 g_W2[P_SZ * F_SZ];   // beta*pw
__device__ float         g_biasP[P_SZ];       // -beta * pws[p]

// ===================== kernel 1: p-side precompute (tf32 wmma) =====================
__global__ __launch_bounds__(256, 1)
void pside_kernel(const float* __restrict__ prototypes,
                  const float* __restrict__ features,
                  const float* __restrict__ alpha,
                  const float* __restrict__ beta,
                  const float* __restrict__ theta) {
    extern __shared__ float smp[];   // ps (16xPS_LD) + Outs (16x512)
    float* ps   = smp;
    float* Outs = smp + 16 * PS_LD;

    int tid  = threadIdx.x;
    int warp = tid >> 5;
    int lane = tid & 31;
    int p0   = blockIdx.x * 16;

    {
        const float4* src = (const float4*)(prototypes + (size_t)p0 * D_SZ);
        for (int i = tid; i < 16 * D_SZ / 4; i += 256) {
            int row = i >> 6, q = i & 63;
            ((float4*)(ps + row * PS_LD))[q] = src[(size_t)row * 64 + q];
        }
    }
    __syncthreads();

    using FragA = wmma::fragment<wmma::matrix_a, 16, 16, 8, wmma::precision::tf32, wmma::row_major>;
    using FragB = wmma::fragment<wmma::matrix_b, 16, 16, 8, wmma::precision::tf32, wmma::col_major>;
    using FragC = wmma::fragment<wmma::accumulator, 16, 16, 8, float>;

    FragC c[4];
#pragma unroll
    for (int j = 0; j < 4; j++) wmma::fill_fragment(c[j], 0.f);

    int f0 = warp * 64;
#pragma unroll 4
    for (int k0 = 0; k0 < D_SZ; k0 += 8) {
        FragA a;
        wmma::load_matrix_sync(a, ps + k0, PS_LD);
#pragma unroll
        for (int e = 0; e < a.num_elements; e++) a.x[e] = wmma::__float_to_tf32(a.x[e]);
#pragma unroll
        for (int j = 0; j < 4; j++) {
            FragB b;
            wmma::load_matrix_sync(b, features + (size_t)(f0 + j * 16) * D_SZ + k0, D_SZ);
#pragma unroll
            for (int e = 0; e < b.num_elements; e++) b.x[e] = wmma::__float_to_tf32(b.x[e]);
            wmma::mma_sync(c[j], a, b, c[j]);
        }
    }
#pragma unroll
    for (int j = 0; j < 4; j++)
        wmma::store_matrix_sync(Outs + f0 + j * 16, c[j], F_SZ, wmma::mem_row_major);
    __syncthreads();

    float a_ = alpha[0], b_ = beta[0], th = theta[0];
    for (int i = tid; i < 16 * F_SZ; i += 256) {
        int pr = i >> 9, f = i & 511;
        float acc = Outs[i];
        float pp = fmaxf(acc, 0.f);
        float pw = acc * pp;
        g_W1[(size_t)(p0 + pr) * F_SZ + f] = __float2bfloat16(th * pw + a_ * pp);
        g_W2[(size_t)(p0 + pr) * F_SZ + f] = __float2bfloat16(b_ * pw);
    }
    for (int r = warp * 2; r < warp * 2 + 2; r++) {
        float s = 0.f;
        for (int cix = lane; cix < F_SZ; cix += 32) {
            float acc = Outs[r * F_SZ + cix];
            s += acc * fmaxf(acc, 0.f);
        }
#pragma unroll
        for (int o = 16; o > 0; o >>= 1) s += __shfl_xor_sync(0xffffffffu, s, o);
        if (lane == 0) g_biasP[p0 + r] = -b_ * s;
    }
}

// ===================== kernel 2: fused, 64-row CTAs, 2 CTA/SM, padded smem =====================
// smem layout:
//   [0, RS_BYTES)    Rs bf16[64][RS_LD]   (epilogue reuses as Os fp32[64][OS_LD], same byte size)
//   [BUF_OFF, ...)   phase A: xs fp32[64][XS_LD] (33,792B) + stw fp32[8][256] (8KB @ +34048)
//                    phase B: Ws1/Ws2 bf16[256][WS_LD] (20,480B each)
//   rb fp32[64], bp fp32[256]
#define RS_BYTES   (64 * RS_LD * 2)                  // 66,560
#define BUF_OFF    RS_BYTES
#define STWP_OFF   (BUF_OFF + 34048)
#define BUF_BYTES  43008                             // >= max(34048+8192, 2*20480)
#define RB_OFF     (BUF_OFF + BUF_BYTES)
#define BP_OFF     (RB_OFF + 256)
#define SMEM_FUSED (BP_OFF + 1024)                   // ≈ 110.6 KB

__global__ __launch_bounds__(256, 2)
void fused_kernel(const float* __restrict__ x,
                  const float* __restrict__ features,
                  const float* __restrict__ alpha,
                  float* __restrict__ out) {
    extern __shared__ char smraw[];
    __nv_bfloat16* Rs = (__nv_bfloat16*)smraw;
    float*         rb = (float*)(smraw + RB_OFF);
    float*         bp = (float*)(smraw + BP_OFF);

    int tid  = threadIdx.x;
    int warp = tid >> 5;
    int lane = tid & 31;
    int m0   = blockIdx.x * 64;

    // ---------------- Phase A: R = relu(x @ F^T), tf32, two f-passes ----------------
    using FA1 = wmma::fragment<wmma::matrix_a, 16, 16, 8, wmma::precision::tf32, wmma::row_major>;
    using FB1 = wmma::fragment<wmma::matrix_b, 16, 16, 8, wmma::precision::tf32, wmma::col_major>;
    using FC1 = wmma::fragment<wmma::accumulator, 16, 16, 8, float>;

    for (int fpass = 0; fpass < 2; fpass++) {
        FC1 c[4][2];                       // 64 rows x 32 cols per warp
#pragma unroll
        for (int i = 0; i < 4; i++)
#pragma unroll
            for (int j = 0; j < 2; j++) wmma::fill_fragment(c[i][j], 0.f);

        int f0 = fpass * 256 + warp * 32;

        for (int kc = 0; kc < 2; kc++) {
            float* xs = (float*)(smraw + BUF_OFF);   // [64][XS_LD]
            __syncthreads();
            {
                const float* src = x + (size_t)m0 * D_SZ + kc * 128;
                for (int i = tid; i < 64 * 32; i += 256) {
                    int row = i >> 5, q = i & 31;    // 32 float4 per row
                    ((float4*)(xs + row * XS_LD))[q] =
                        ((const float4*)(src + (size_t)row * D_SZ))[q];
                }
            }
            __syncthreads();

#pragma unroll 4
            for (int k0 = 0; k0 < 128; k0 += 8) {
                FA1 a[4];
#pragma unroll
                for (int i = 0; i < 4; i++) {
                    wmma::load_matrix_sync(a[i], xs + (i * 16) * XS_LD + k0, XS_LD);
#pragma unroll
                    for (int e = 0; e < a[i].num_elements; e++)
                        a[i].x[e] = wmma::__float_to_tf32(a[i].x[e]);
                }
#pragma unroll
                for (int j = 0; j < 2; j++) {
                    FB1 b;
                    wmma::load_matrix_sync(b, features + (size_t)(f0 + j * 16) * D_SZ + kc * 128 + k0, D_SZ);
#pragma unroll
                    for (int e = 0; e < b.num_elements; e++)
                        b.x[e] = wmma::__float_to_tf32(b.x[e]);
#pragma unroll
                    for (int i = 0; i < 4; i++) wmma::mma_sync(c[i][j], a[i], b, c[i][j]);
                }
            }
        }

        // epilogue: frags -> per-warp staging -> relu -> bf16 Rs
        float* stw = (float*)(smraw + STWP_OFF) + warp * 256;
#pragma unroll
        for (int i = 0; i < 4; i++) {
#pragma unroll
            for (int j = 0; j < 2; j++) {
                wmma::store_matrix_sync(stw, c[i][j], 16, wmma::mem_row_major);
                __syncwarp();
#pragma unroll
                for (int e = 0; e < 8; e++) {
                    int idx = lane * 8 + e;
                    int rr = idx >> 4, cc = idx & 15;
                    float v = fmaxf(stw[idx], 0.f);
                    Rs[(i * 16 + rr) * RS_LD + f0 + j * 16 + cc] = __float2bfloat16(v);
                }
                __syncwarp();
            }
        }
    }
    __syncthreads();   // Rs complete

    // row bias: rb[r] = -alpha * sum_f r^2 (warp w -> rows w*8..+8)
    {
        float av = alpha[0];
        for (int r = warp * 8; r < warp * 8 + 8; r++) {
            float s = 0.f;
            for (int cix = lane; cix < F_SZ; cix += 32) {
                float v = __bfloat162float(Rs[r * RS_LD + cix]);
                s += v * v;
            }
#pragma unroll
            for (int o = 16; o > 0; o >>= 1) s += __shfl_xor_sync(0xffffffffu, s, o);
            if (lane == 0) rb[r] = -av * s;
        }
    }
    if (tid < P_SZ) bp[tid] = g_biasP[tid];

    // ---------------- Phase B: out = [R^2|R] @ [W1|W2]^T, bf16, 32x64 warp tiles ----------------
    using FA2 = wmma::fragment<wmma::matrix_a, 16, 16, 16, __nv_bfloat16, wmma::row_major>;
    using FB2 = wmma::fragment<wmma::matrix_b, 16, 16, 16, __nv_bfloat16, wmma::col_major>;
    using FC2 = wmma::fragment<wmma::accumulator, 16, 16, 16, float>;

    __nv_bfloat16* Ws1 = (__nv_bfloat16*)(smraw + BUF_OFF);
    __nv_bfloat16* Ws2 = Ws1 + P_SZ * WS_LD;

    int wm = warp >> 2;      // 0..1 -> 32-row slab
    int wn = warp & 3;       // 0..3 -> 64-col slab
    int mrow = wm * 32, ncol = wn * 64;

    FC2 c2[2][4];
#pragma unroll
    for (int i = 0; i < 2; i++)
#pragma unroll
        for (int j = 0; j < 4; j++) wmma::fill_fragment(c2[i][j], 0.f);

    for (int kc = 0; kc < F_SZ; kc += 32) {
        __syncthreads();
        {
            for (int i = tid; i < P_SZ * 4; i += 256) {   // 4 float4 (=32 bf16) per row
                int n = i >> 2, q = i & 3;
                ((float4*)(Ws1 + n * WS_LD))[q] = ((const float4*)(g_W1 + (size_t)n * F_SZ + kc))[q];
                ((float4*)(Ws2 + n * WS_LD))[q] = ((const float4*)(g_W2 + (size_t)n * F_SZ + kc))[q];
            }
        }
        __syncthreads();

#pragma unroll
        for (int k0 = 0; k0 < 32; k0 += 16) {
            FA2 a[2], a2[2];
#pragma unroll
            for (int i = 0; i < 2; i++) {
                wmma::load_matrix_sync(a[i], Rs + (mrow + i * 16) * RS_LD + kc + k0, RS_LD);
#pragma unroll
                for (int e = 0; e < a[i].num_elements; e++)
                    a2[i].x[e] = a[i].x[e] * a[i].x[e];
            }
#pragma unroll
            for (int j = 0; j < 4; j++) {
                FB2 b1, b2;
                wmma::load_matrix_sync(b1, Ws1 + (ncol + j * 16) * WS_LD + k0, WS_LD);
                wmma::load_matrix_sync(b2, Ws2 + (ncol + j * 16) * WS_LD + k0, WS_LD);
#pragma unroll
                for (int i = 0; i < 2; i++) {
                    wmma::mma_sync(c2[i][j], a2[i], b1, c2[i][j]);
                    wmma::mma_sync(c2[i][j], a[i], b2, c2[i][j]);
                }
            }
        }
    }
    __syncthreads();   // Rs dead -> Os takes over

    float* Os = (float*)smraw;   // [64][OS_LD] fp32 (same 66,560 B footprint)
#pragma unroll
    for (int i = 0; i < 2; i++)
#pragma unroll
        for (int j = 0; j < 4; j++)
            wmma::store_matrix_sync(Os + (mrow + i * 16) * OS_LD + ncol + j * 16, c2[i][j],
                                    OS_LD, wmma::mem_row_major);
    __syncthreads();

    for (int i = tid; i < 64 * P_SZ; i += 256) {
        int r = i >> 8;
        int p = i & 255;
        out[(size_t)(m0 + r) * P_SZ + p] = Os[r * OS_LD + p] + rb[r] + bp[p];
    }
}

// =========================== launch ===========================
extern "C" void kernel_launch(void* const* d_in, const int* in_sizes, int n_in,
                              void* d_out, int out_size) {
    const float* x          = (const float*)d_in[0];
    const float* features   = (const float*)d_in[1];
    const float* prototypes = (const float*)d_in[2];
    const float* alpha      = (const float*)d_in[3];
    const float* beta       = (const float*)d_in[4];
    const float* theta      = (const float*)d_in[5];
    float* out = (float*)d_out;

    cudaFuncSetAttribute(pside_kernel, cudaFuncAttributeMaxDynamicSharedMemorySize, 64 * 1024);
    cudaFuncSetAttribute(fused_kernel, cudaFuncAttributeMaxDynamicSharedMemorySize, SMEM_FUSED);

    pside_kernel<<<P_SZ / 16, 256, 64 * 1024>>>(prototypes, features, alpha, beta, theta);
    fused_kernel<<<B_SZ / 64, 256, SMEM_FUSED>>>(x, features, alpha, out);
}

// round 9
// speedup vs baseline: 3.3305x; 1.3598x over previous
#include <cuda_runtime.h>
#include <cuda_bf16.h>
#include <cuda_fp16.h>
#include <mma.h>
#include <cstdint>

using namespace nvcuda;

#define B_SZ 65536
#define D_SZ 256
#define F_SZ 512
#define P_SZ 256

// padded smem strides — all row strides odd in 16B units => conflict-free
#define RS_LD  520   // bf16: 1040B = 65 units
#define XS_LD  264   // fp16: 528B  = 33 units
#define WS_LD  40    // bf16: 80B   = 5 units
#define OS_LD  260   // fp32: 1040B = 65 units
#define PS_LD  260   // pside fp32

// ---------------- scratch (static device globals; no allocations) ----------------
__device__ __nv_bfloat16 g_W1[P_SZ * F_SZ];   // theta*pw + alpha*pp
__device__ __nv_bfloat16 g_W2[P_SZ * F_SZ];   // beta*pw
__device__ float         g_biasP[P_SZ];       // -beta * pws[p]
__device__ __half        g_Fh[F_SZ * D_SZ];   // features in fp16 (for stage-1 B operand)

// ===================== kernel 0: features fp32 -> fp16 =====================
__global__ __launch_bounds__(256)
void fconv_kernel(const float* __restrict__ features) {
    int i = blockIdx.x * 256 + threadIdx.x;     // one float4 (4 elems) per thread
    float4 v = ((const float4*)features)[i];
    __half2 h0 = __floats2half2_rn(v.x, v.y);
    __half2 h1 = __floats2half2_rn(v.z, v.w);
    uint2 w;
    w.x = *reinterpret_cast<uint32_t*>(&h0);
    w.y = *reinterpret_cast<uint32_t*>(&h1);
    ((uint2*)g_Fh)[i] = w;
}

// ===================== kernel 1: p-side precompute (tf32 wmma) =====================
__global__ __launch_bounds__(256, 1)
void pside_kernel(const float* __restrict__ prototypes,
                  const float* __restrict__ features,
                  const float* __restrict__ alpha,
                  const float* __restrict__ beta,
                  const float* __restrict__ theta) {
    extern __shared__ float smp[];   // ps (16xPS_LD) + Outs (16x512)
    float* ps   = smp;
    float* Outs = smp + 16 * PS_LD;

    int tid  = threadIdx.x;
    int warp = tid >> 5;
    int lane = tid & 31;
    int p0   = blockIdx.x * 16;

    {
        const float4* src = (const float4*)(prototypes + (size_t)p0 * D_SZ);
        for (int i = tid; i < 16 * D_SZ / 4; i += 256) {
            int row = i >> 6, q = i & 63;
            ((float4*)(ps + row * PS_LD))[q] = src[(size_t)row * 64 + q];
        }
    }
    __syncthreads();

    using FragA = wmma::fragment<wmma::matrix_a, 16, 16, 8, wmma::precision::tf32, wmma::row_major>;
    using FragB = wmma::fragment<wmma::matrix_b, 16, 16, 8, wmma::precision::tf32, wmma::col_major>;
    using FragC = wmma::fragment<wmma::accumulator, 16, 16, 8, float>;

    FragC c[4];
#pragma unroll
    for (int j = 0; j < 4; j++) wmma::fill_fragment(c[j], 0.f);

    int f0 = warp * 64;
#pragma unroll 4
    for (int k0 = 0; k0 < D_SZ; k0 += 8) {
        FragA a;
        wmma::load_matrix_sync(a, ps + k0, PS_LD);
#pragma unroll
        for (int e = 0; e < a.num_elements; e++) a.x[e] = wmma::__float_to_tf32(a.x[e]);
#pragma unroll
        for (int j = 0; j < 4; j++) {
            FragB b;
            wmma::load_matrix_sync(b, features + (size_t)(f0 + j * 16) * D_SZ + k0, D_SZ);
#pragma unroll
            for (int e = 0; e < b.num_elements; e++) b.x[e] = wmma::__float_to_tf32(b.x[e]);
            wmma::mma_sync(c[j], a, b, c[j]);
        }
    }
#pragma unroll
    for (int j = 0; j < 4; j++)
        wmma::store_matrix_sync(Outs + f0 + j * 16, c[j], F_SZ, wmma::mem_row_major);
    __syncthreads();

    float a_ = alpha[0], b_ = beta[0], th = theta[0];
    for (int i = tid; i < 16 * F_SZ; i += 256) {
        int pr = i >> 9, f = i & 511;
        float acc = Outs[i];
        float pp = fmaxf(acc, 0.f);
        float pw = acc * pp;
        g_W1[(size_t)(p0 + pr) * F_SZ + f] = __float2bfloat16(th * pw + a_ * pp);
        g_W2[(size_t)(p0 + pr) * F_SZ + f] = __float2bfloat16(b_ * pw);
    }
    for (int r = warp * 2; r < warp * 2 + 2; r++) {
        float s = 0.f;
        for (int cix = lane; cix < F_SZ; cix += 32) {
            float acc = Outs[r * F_SZ + cix];
            s += acc * fmaxf(acc, 0.f);
        }
#pragma unroll
        for (int o = 16; o > 0; o >>= 1) s += __shfl_xor_sync(0xffffffffu, s, o);
        if (lane == 0) g_biasP[p0 + r] = -b_ * s;
    }
}

// ===================== kernel 2: fused, 64-row CTAs, 2 CTA/SM, fp16 stage-1 =====================
// smem layout:
//   [0, RS_BYTES)    Rs bf16[64][RS_LD]   (epilogue reuses as Os fp32[64][OS_LD])
//   [BUF_OFF, ...)   phase A: xs fp16[64][XS_LD] (33,792B) + stw fp32[8][256] (8KB @ +34048)
//                    phase B: Ws1/Ws2 bf16[256][WS_LD] (20,480B each)
//   rb fp32[64], bp fp32[256]
#define RS_BYTES   (64 * RS_LD * 2)                  // 66,560
#define BUF_OFF    RS_BYTES
#define STWP_OFF   (BUF_OFF + 34048)
#define BUF_BYTES  43008
#define RB_OFF     (BUF_OFF + BUF_BYTES)
#define BP_OFF     (RB_OFF + 256)
#define SMEM_FUSED (BP_OFF + 1024)                   // ≈ 110.6 KB

__global__ __launch_bounds__(256, 2)
void fused_kernel(const float* __restrict__ x,
                  const float* __restrict__ alpha,
                  float* __restrict__ out) {
    extern __shared__ char smraw[];
    __nv_bfloat16* Rs = (__nv_bfloat16*)smraw;
    float*         rb = (float*)(smraw + RB_OFF);
    float*         bp = (float*)(smraw + BP_OFF);

    int tid  = threadIdx.x;
    int warp = tid >> 5;
    int lane = tid & 31;
    int m0   = blockIdx.x * 64;

    // ---------------- Phase A: R = relu(x @ F^T), fp16 m16n16k16, two f-passes ----------------
    using FA1 = wmma::fragment<wmma::matrix_a, 16, 16, 16, __half, wmma::row_major>;
    using FB1 = wmma::fragment<wmma::matrix_b, 16, 16, 16, __half, wmma::col_major>;
    using FC1 = wmma::fragment<wmma::accumulator, 16, 16, 16, float>;

    __half* xs = (__half*)(smraw + BUF_OFF);   // [64][XS_LD] fp16, entire K resident
    {
        const float4* src = (const float4*)(x + (size_t)m0 * D_SZ);
        for (int i = tid; i < 64 * 64; i += 256) {    // 64 rows x 64 float4
            int row = i >> 6, q = i & 63;
            float4 v = src[(size_t)row * 64 + q];
            __half2 h0 = __floats2half2_rn(v.x, v.y);
            __half2 h1 = __floats2half2_rn(v.z, v.w);
            uint2 w;
            w.x = *reinterpret_cast<uint32_t*>(&h0);
            w.y = *reinterpret_cast<uint32_t*>(&h1);
            *(uint2*)(xs + row * XS_LD + q * 4) = w;
        }
    }
    __syncthreads();

    for (int fpass = 0; fpass < 2; fpass++) {
        FC1 c[4][2];                       // 64 rows x 32 cols per warp
#pragma unroll
        for (int i = 0; i < 4; i++)
#pragma unroll
            for (int j = 0; j < 2; j++) wmma::fill_fragment(c[i][j], 0.f);

        int f0 = fpass * 256 + warp * 32;

#pragma unroll 2
        for (int k0 = 0; k0 < D_SZ; k0 += 16) {
            FA1 a[4];
#pragma unroll
            for (int i = 0; i < 4; i++)
                wmma::load_matrix_sync(a[i], xs + (i * 16) * XS_LD + k0, XS_LD);
#pragma unroll
            for (int j = 0; j < 2; j++) {
                FB1 b;
                wmma::load_matrix_sync(b, g_Fh + (size_t)(f0 + j * 16) * D_SZ + k0, D_SZ);
#pragma unroll
                for (int i = 0; i < 4; i++) wmma::mma_sync(c[i][j], a[i], b, c[i][j]);
            }
        }

        // epilogue: frags -> per-warp staging -> relu -> bf16 Rs
        float* stw = (float*)(smraw + STWP_OFF) + warp * 256;
#pragma unroll
        for (int i = 0; i < 4; i++) {
#pragma unroll
            for (int j = 0; j < 2; j++) {
                wmma::store_matrix_sync(stw, c[i][j], 16, wmma::mem_row_major);
                __syncwarp();
#pragma unroll
                for (int e = 0; e < 8; e++) {
                    int idx = lane * 8 + e;
                    int rr = idx >> 4, cc = idx & 15;
                    float v = fmaxf(stw[idx], 0.f);
                    Rs[(i * 16 + rr) * RS_LD + f0 + j * 16 + cc] = __float2bfloat16(v);
                }
                __syncwarp();
            }
        }
    }
    __syncthreads();   // Rs complete; xs/stw dead

    // row bias: rb[r] = -alpha * sum_f r^2 (warp w -> rows w*8..+8)
    {
        float av = alpha[0];
        for (int r = warp * 8; r < warp * 8 + 8; r++) {
            float s = 0.f;
            for (int cix = lane; cix < F_SZ; cix += 32) {
                float v = __bfloat162float(Rs[r * RS_LD + cix]);
                s += v * v;
            }
#pragma unroll
            for (int o = 16; o > 0; o >>= 1) s += __shfl_xor_sync(0xffffffffu, s, o);
            if (lane == 0) rb[r] = -av * s;
        }
    }
    if (tid < P_SZ) bp[tid] = g_biasP[tid];

    // ---------------- Phase B: out = [R^2|R] @ [W1|W2]^T, bf16, 32x64 warp tiles ----------------
    using FA2 = wmma::fragment<wmma::matrix_a, 16, 16, 16, __nv_bfloat16, wmma::row_major>;
    using FB2 = wmma::fragment<wmma::matrix_b, 16, 16, 16, __nv_bfloat16, wmma::col_major>;
    using FC2 = wmma::fragment<wmma::accumulator, 16, 16, 16, float>;

    __nv_bfloat16* Ws1 = (__nv_bfloat16*)(smraw + BUF_OFF);
    __nv_bfloat16* Ws2 = Ws1 + P_SZ * WS_LD;

    int wm = warp >> 2;      // 0..1 -> 32-row slab
    int wn = warp & 3;       // 0..3 -> 64-col slab
    int mrow = wm * 32, ncol = wn * 64;

    FC2 c2[2][4];
#pragma unroll
    for (int i = 0; i < 2; i++)
#pragma unroll
        for (int j = 0; j < 4; j++) wmma::fill_fragment(c2[i][j], 0.f);

    for (int kc = 0; kc < F_SZ; kc += 32) {
        __syncthreads();
        {
            for (int i = tid; i < P_SZ * 4; i += 256) {   // 4 float4 (=32 bf16) per row
                int n = i >> 2, q = i & 3;
                ((float4*)(Ws1 + n * WS_LD))[q] = ((const float4*)(g_W1 + (size_t)n * F_SZ + kc))[q];
                ((float4*)(Ws2 + n * WS_LD))[q] = ((const float4*)(g_W2 + (size_t)n * F_SZ + kc))[q];
            }
        }
        __syncthreads();

#pragma unroll
        for (int k0 = 0; k0 < 32; k0 += 16) {
            FA2 a[2], a2[2];
#pragma unroll
            for (int i = 0; i < 2; i++) {
                wmma::load_matrix_sync(a[i], Rs + (mrow + i * 16) * RS_LD + kc + k0, RS_LD);
#pragma unroll
                for (int e = 0; e < a[i].num_elements; e++)
                    a2[i].x[e] = a[i].x[e] * a[i].x[e];
            }
#pragma unroll
            for (int j = 0; j < 4; j++) {
                FB2 b1, b2;
                wmma::load_matrix_sync(b1, Ws1 + (ncol + j * 16) * WS_LD + k0, WS_LD);
                wmma::load_matrix_sync(b2, Ws2 + (ncol + j * 16) * WS_LD + k0, WS_LD);
#pragma unroll
                for (int i = 0; i < 2; i++) {
                    wmma::mma_sync(c2[i][j], a2[i], b1, c2[i][j]);
                    wmma::mma_sync(c2[i][j], a[i], b2, c2[i][j]);
                }
            }
        }
    }
    __syncthreads();   // Rs dead -> Os takes over

    float* Os = (float*)smraw;   // [64][OS_LD] fp32
#pragma unroll
    for (int i = 0; i < 2; i++)
#pragma unroll
        for (int j = 0; j < 4; j++)
            wmma::store_matrix_sync(Os + (mrow + i * 16) * OS_LD + ncol + j * 16, c2[i][j],
                                    OS_LD, wmma::mem_row_major);
    __syncthreads();

    for (int i = tid; i < 64 * P_SZ; i += 256) {
        int r = i >> 8;
        int p = i & 255;
        out[(size_t)(m0 + r) * P_SZ + p] = Os[r * OS_LD + p] + rb[r] + bp[p];
    }
}

// =========================== launch ===========================
extern "C" void kernel_launch(void* const* d_in, const int* in_sizes, int n_in,
                              void* d_out, int out_size) {
    const float* x          = (const float*)d_in[0];
    const float* features   = (const float*)d_in[1];
    const float* prototypes = (const float*)d_in[2];
    const float* alpha      = (const float*)d_in[3];
    const float* beta       = (const float*)d_in[4];
    const float* theta      = (const float*)d_in[5];
    float* out = (float*)d_out;

    cudaFuncSetAttribute(pside_kernel, cudaFuncAttributeMaxDynamicSharedMemorySize, 64 * 1024);
    cudaFuncSetAttribute(fused_kernel, cudaFuncAttributeMaxDynamicSharedMemorySize, SMEM_FUSED);

    fconv_kernel<<<F_SZ * D_SZ / 4 / 256, 256>>>(features);
    pside_kernel<<<P_SZ / 16, 256, 64 * 1024>>>(prototypes, features, alpha, beta, theta);
    fused_kernel<<<B_SZ / 64, 256, SMEM_FUSED>>>(x, alpha, out);
}

// round 10
// speedup vs baseline: 3.6390x; 1.0926x over previous
#include <cuda_runtime.h>
#include <cuda_bf16.h>
#include <cuda_fp16.h>
#include <mma.h>
#include <cstdint>

using namespace nvcuda;

#define B_SZ 65536
#define D_SZ 256
#define F_SZ 512
#define P_SZ 256

// padded smem strides — all row strides odd in 16B units => conflict-free
#define RS_LD  520   // bf16: 1040B = 65 units
#define XS_LD  264   // fp16: 528B  = 33 units
#define OS_LD  260   // fp32: 1040B = 65 units
#define PS_LD  260   // pside fp32

// ---------------- scratch (static device globals; no allocations) ----------------
__device__ __nv_bfloat16 g_W1[P_SZ * F_SZ];   // theta*pw + alpha*pp
__device__ __nv_bfloat16 g_W2[P_SZ * F_SZ];   // beta*pw
__device__ float         g_biasP[P_SZ];       // -beta * pws[p]
__device__ __half        g_Fh[F_SZ * D_SZ];   // features in fp16 (stage-1 B operand)

// ===================== kernel 0: features fp32 -> fp16 =====================
__global__ __launch_bounds__(256)
void fconv_kernel(const float* __restrict__ features) {
    int i = blockIdx.x * 256 + threadIdx.x;
    float4 v = ((const float4*)features)[i];
    __half2 h0 = __floats2half2_rn(v.x, v.y);
    __half2 h1 = __floats2half2_rn(v.z, v.w);
    uint2 w;
    w.x = *reinterpret_cast<uint32_t*>(&h0);
    w.y = *reinterpret_cast<uint32_t*>(&h1);
    ((uint2*)g_Fh)[i] = w;
}

// ===================== kernel 1: p-side precompute (tf32 wmma) =====================
__global__ __launch_bounds__(256, 1)
void pside_kernel(const float* __restrict__ prototypes,
                  const float* __restrict__ features,
                  const float* __restrict__ alpha,
                  const float* __restrict__ beta,
                  const float* __restrict__ theta) {
    extern __shared__ float smp[];
    float* ps   = smp;
    float* Outs = smp + 16 * PS_LD;

    int tid  = threadIdx.x;
    int warp = tid >> 5;
    int lane = tid & 31;
    int p0   = blockIdx.x * 16;

    {
        const float4* src = (const float4*)(prototypes + (size_t)p0 * D_SZ);
        for (int i = tid; i < 16 * D_SZ / 4; i += 256) {
            int row = i >> 6, q = i & 63;
            ((float4*)(ps + row * PS_LD))[q] = src[(size_t)row * 64 + q];
        }
    }
    __syncthreads();

    using FragA = wmma::fragment<wmma::matrix_a, 16, 16, 8, wmma::precision::tf32, wmma::row_major>;
    using FragB = wmma::fragment<wmma::matrix_b, 16, 16, 8, wmma::precision::tf32, wmma::col_major>;
    using FragC = wmma::fragment<wmma::accumulator, 16, 16, 8, float>;

    FragC c[4];
#pragma unroll
    for (int j = 0; j < 4; j++) wmma::fill_fragment(c[j], 0.f);

    int f0 = warp * 64;
#pragma unroll 4
    for (int k0 = 0; k0 < D_SZ; k0 += 8) {
        FragA a;
        wmma::load_matrix_sync(a, ps + k0, PS_LD);
#pragma unroll
        for (int e = 0; e < a.num_elements; e++) a.x[e] = wmma::__float_to_tf32(a.x[e]);
#pragma unroll
        for (int j = 0; j < 4; j++) {
            FragB b;
            wmma::load_matrix_sync(b, features + (size_t)(f0 + j * 16) * D_SZ + k0, D_SZ);
#pragma unroll
            for (int e = 0; e < b.num_elements; e++) b.x[e] = wmma::__float_to_tf32(b.x[e]);
            wmma::mma_sync(c[j], a, b, c[j]);
        }
    }
#pragma unroll
    for (int j = 0; j < 4; j++)
        wmma::store_matrix_sync(Outs + f0 + j * 16, c[j], F_SZ, wmma::mem_row_major);
    __syncthreads();

    float a_ = alpha[0], b_ = beta[0], th = theta[0];
    for (int i = tid; i < 16 * F_SZ; i += 256) {
        int pr = i >> 9, f = i & 511;
        float acc = Outs[i];
        float pp = fmaxf(acc, 0.f);
        float pw = acc * pp;
        g_W1[(size_t)(p0 + pr) * F_SZ + f] = __float2bfloat16(th * pw + a_ * pp);
        g_W2[(size_t)(p0 + pr) * F_SZ + f] = __float2bfloat16(b_ * pw);
    }
    for (int r = warp * 2; r < warp * 2 + 2; r++) {
        float s = 0.f;
        for (int cix = lane; cix < F_SZ; cix += 32) {
            float acc = Outs[r * F_SZ + cix];
            s += acc * fmaxf(acc, 0.f);
        }
#pragma unroll
        for (int o = 16; o > 0; o >>= 1) s += __shfl_xor_sync(0xffffffffu, s, o);
        if (lane == 0) g_biasP[p0 + r] = -b_ * s;
    }
}

// ===================== kernel 2: fused, 64-row CTAs, 2 CTA/SM =====================
// smem:
//   [0, RS_BYTES)    Rs bf16[64][RS_LD]   (epilogue reuses as Os fp32[64][OS_LD])
//   [BUF_OFF, ...)   phase A only: xs fp16[64][XS_LD] (33,792B) + stw fp32[8][256]
//   rb fp32[64], bp fp32[256]
#define RS_BYTES   (64 * RS_LD * 2)                  // 66,560
#define BUF_OFF    RS_BYTES
#define STWP_OFF   (BUF_OFF + 34048)
#define BUF_BYTES  (34048 + 8192)
#define RB_OFF     (BUF_OFF + BUF_BYTES)
#define BP_OFF     (RB_OFF + 256)
#define SMEM_FUSED (BP_OFF + 1024)                   // ≈ 107 KB

__global__ __launch_bounds__(256, 2)
void fused_kernel(const float* __restrict__ x,
                  const float* __restrict__ alpha,
                  float* __restrict__ out) {
    extern __shared__ char smraw[];
    __nv_bfloat16* Rs = (__nv_bfloat16*)smraw;
    float*         rb = (float*)(smraw + RB_OFF);
    float*         bp = (float*)(smraw + BP_OFF);

    int tid  = threadIdx.x;
    int warp = tid >> 5;
    int lane = tid & 31;
    int m0   = blockIdx.x * 64;

    // ---------------- Phase A: R = relu(x @ F^T), fp16 m16n16k16, two f-passes ----------------
    using FA1 = wmma::fragment<wmma::matrix_a, 16, 16, 16, __half, wmma::row_major>;
    using FB1 = wmma::fragment<wmma::matrix_b, 16, 16, 16, __half, wmma::col_major>;
    using FC1 = wmma::fragment<wmma::accumulator, 16, 16, 16, float>;

    __half* xs = (__half*)(smraw + BUF_OFF);   // [64][XS_LD] fp16, whole K resident
    {
        const float4* src = (const float4*)(x + (size_t)m0 * D_SZ);
        for (int i = tid; i < 64 * 64; i += 256) {
            int row = i >> 6, q = i & 63;
            float4 v = src[(size_t)row * 64 + q];
            __half2 h0 = __floats2half2_rn(v.x, v.y);
            __half2 h1 = __floats2half2_rn(v.z, v.w);
            uint2 w;
            w.x = *reinterpret_cast<uint32_t*>(&h0);
            w.y = *reinterpret_cast<uint32_t*>(&h1);
            *(uint2*)(xs + row * XS_LD + q * 4) = w;
        }
    }
    __syncthreads();

    for (int fpass = 0; fpass < 2; fpass++) {
        FC1 c[4][2];
#pragma unroll
        for (int i = 0; i < 4; i++)
#pragma unroll
            for (int j = 0; j < 2; j++) wmma::fill_fragment(c[i][j], 0.f);

        int f0 = fpass * 256 + warp * 32;

#pragma unroll 2
        for (int k0 = 0; k0 < D_SZ; k0 += 16) {
            FA1 a[4];
#pragma unroll
            for (int i = 0; i < 4; i++)
                wmma::load_matrix_sync(a[i], xs + (i * 16) * XS_LD + k0, XS_LD);
#pragma unroll
            for (int j = 0; j < 2; j++) {
                FB1 b;
                wmma::load_matrix_sync(b, g_Fh + (size_t)(f0 + j * 16) * D_SZ + k0, D_SZ);
#pragma unroll
                for (int i = 0; i < 4; i++) wmma::mma_sync(c[i][j], a[i], b, c[i][j]);
            }
        }

        float* stw = (float*)(smraw + STWP_OFF) + warp * 256;
#pragma unroll
        for (int i = 0; i < 4; i++) {
#pragma unroll
            for (int j = 0; j < 2; j++) {
                wmma::store_matrix_sync(stw, c[i][j], 16, wmma::mem_row_major);
                __syncwarp();
#pragma unroll
                for (int e = 0; e < 8; e++) {
                    int idx = lane * 8 + e;
                    int rr = idx >> 4, cc = idx & 15;
                    float v = fmaxf(stw[idx], 0.f);
                    Rs[(i * 16 + rr) * RS_LD + f0 + j * 16 + cc] = __float2bfloat16(v);
                }
                __syncwarp();
            }
        }
    }
    __syncthreads();   // Rs complete; xs/stw dead

    // row bias
    {
        float av = alpha[0];
        for (int r = warp * 8; r < warp * 8 + 8; r++) {
            float s = 0.f;
            for (int cix = lane; cix < F_SZ; cix += 32) {
                float v = __bfloat162float(Rs[r * RS_LD + cix]);
                s += v * v;
            }
#pragma unroll
            for (int o = 16; o > 0; o >>= 1) s += __shfl_xor_sync(0xffffffffu, s, o);
            if (lane == 0) rb[r] = -av * s;
        }
    }
    if (tid < P_SZ) bp[tid] = g_biasP[tid];

    // ---------------- Phase B: out = [R^2|R] @ [W1|W2]^T, bf16, 64x32 warp tiles ----------------
    // Warp w owns all 64 rows x N-cols [w*32, w*32+32). W fragments loaded DIRECTLY from
    // global (L2-resident, shared by all CTAs) — no smem staging, no syncs in the k-loop.
    using FA2 = wmma::fragment<wmma::matrix_a, 16, 16, 16, __nv_bfloat16, wmma::row_major>;
    using FB2 = wmma::fragment<wmma::matrix_b, 16, 16, 16, __nv_bfloat16, wmma::col_major>;
    using FC2 = wmma::fragment<wmma::accumulator, 16, 16, 16, float>;

    int ncol = warp * 32;

    FC2 c2[4][2];
#pragma unroll
    for (int i = 0; i < 4; i++)
#pragma unroll
        for (int j = 0; j < 2; j++) wmma::fill_fragment(c2[i][j], 0.f);

#pragma unroll 2
    for (int k0 = 0; k0 < F_SZ; k0 += 16) {
        FA2 a[4], a2[4];
#pragma unroll
        for (int i = 0; i < 4; i++) {
            wmma::load_matrix_sync(a[i], Rs + (i * 16) * RS_LD + k0, RS_LD);
#pragma unroll
            for (int e = 0; e < a[i].num_elements; e++)
                a2[i].x[e] = a[i].x[e] * a[i].x[e];
        }
#pragma unroll
        for (int j = 0; j < 2; j++) {
            FB2 b1, b2;
            wmma::load_matrix_sync(b1, g_W1 + (size_t)(ncol + j * 16) * F_SZ + k0, F_SZ);
            wmma::load_matrix_sync(b2, g_W2 + (size_t)(ncol + j * 16) * F_SZ + k0, F_SZ);
#pragma unroll
            for (int i = 0; i < 4; i++) {
                wmma::mma_sync(c2[i][j], a2[i], b1, c2[i][j]);
                wmma::mma_sync(c2[i][j], a[i], b2, c2[i][j]);
            }
        }
    }
    __syncthreads();   // all warps done reading Rs -> Os takes over the buffer

    float* Os = (float*)smraw;   // [64][OS_LD] fp32
#pragma unroll
    for (int i = 0; i < 4; i++)
#pragma unroll
        for (int j = 0; j < 2; j++)
            wmma::store_matrix_sync(Os + (i * 16) * OS_LD + ncol + j * 16, c2[i][j],
                                    OS_LD, wmma::mem_row_major);
    __syncthreads();

    for (int i = tid; i < 64 * P_SZ; i += 256) {
        int r = i >> 8;
        int p = i & 255;
        out[(size_t)(m0 + r) * P_SZ + p] = Os[r * OS_LD + p] + rb[r] + bp[p];
    }
}

// =========================== launch ===========================
extern "C" void kernel_launch(void* const* d_in, const int* in_sizes, int n_in,
                              void* d_out, int out_size) {
    const float* x          = (const float*)d_in[0];
    const float* features   = (const float*)d_in[1];
    const float* prototypes = (const float*)d_in[2];
    const float* alpha      = (const float*)d_in[3];
    const float* beta       = (const float*)d_in[4];
    const float* theta      = (const float*)d_in[5];
    float* out = (float*)d_out;

    cudaFuncSetAttribute(pside_kernel, cudaFuncAttributeMaxDynamicSharedMemorySize, 64 * 1024);
    cudaFuncSetAttribute(fused_kernel, cudaFuncAttributeMaxDynamicSharedMemorySize, SMEM_FUSED);

    fconv_kernel<<<F_SZ * D_SZ / 4 / 256, 256>>>(features);
    pside_kernel<<<P_SZ / 16, 256, 64 * 1024>>>(prototypes, features, alpha, beta, theta);
    fused_kernel<<<B_SZ / 64, 256, SMEM_FUSED>>>(x, alpha, out);
}